// round 16
// baseline (speedup 1.0000x reference)
#include <cuda_runtime.h>
#include <cuda_fp16.h>
#include <mma.h>
#include <cstdint>

#define N_NODES 100000
#define N_PAD   100096        // multiple of 128-row tiles
#define N_EDGES 1600000
#define D 128
#define SCAN_B 1024
#define N_SCAN_BLOCKS ((N_NODES + SCAN_B - 1) / SCAN_B)   // 98
#define C0N 50048             // chunk0 rows/nodes (391 gemm tiles)
#define C1N (N_NODES - C0N)   // 49952 nodes (chunk1 gemm covers to N_PAD)

using namespace nvcuda;

// Scratch (allocation-free rule: __device__ globals; zero-initialized)
__device__ __half g_hs0[(size_t)N_PAD * D];  // hs buffer, layers 0 & 2
__device__ __half g_hs1[(size_t)N_PAD * D];  // hs buffer, layer 1
__device__ __half g_xh[(size_t)N_PAD * D];   // activations, fp16 (pad rows 0)
__device__ __half g_w16[3 * D * D];          // weights, fp16
__device__ float  g_dinv[N_NODES];
__device__ int    g_is64;
__device__ unsigned g_epack[N_EDGES];        // (col<<15) | slot
__device__ int    g_cnt[N_NODES];
__device__ int    g_rowptr[N_NODES + 1];
__device__ int    g_src[N_EDGES];
__device__ int    g_bsum[N_SCAN_BLOCKS];

// ===========================================================================
// Setup (proven R12/R15 kernels)
// ===========================================================================
__global__ void k_detect_zero(const unsigned int* __restrict__ buf) {
    int i = blockIdx.x * blockDim.x + threadIdx.x;
    if (i < N_NODES) g_cnt[i] = 0;
    if (blockIdx.x == 0) {
        __shared__ unsigned int acc;
        if (threadIdx.x == 0) acc = 0u;
        __syncthreads();
        unsigned int local = 0u;
        for (int k = threadIdx.x; k < 4096; k += blockDim.x)
            local |= buf[2 * k + 1];
        atomicOr(&acc, local);
        __syncthreads();
        if (threadIdx.x == 0) g_is64 = (acc == 0u) ? 1 : 0;
    }
}

__global__ void k_hist_pack(const void* __restrict__ buf) {
    int e = blockIdx.x * blockDim.x + threadIdx.x;
    if (e >= N_EDGES) return;
    int c;
    if (g_is64) c = (int)((const long long*)buf)[e + N_EDGES];
    else        c = ((const int*)buf)[e + N_EDGES];
    int pos = atomicAdd(&g_cnt[c], 1);
    g_epack[e] = ((unsigned)c << 15) | ((unsigned)pos & 0x7FFFu);
}

__global__ void __launch_bounds__(SCAN_B)
k_scan1() {
    __shared__ int s[SCAN_B];
    int i = blockIdx.x * SCAN_B + threadIdx.x;
    int v = (i < N_NODES) ? g_cnt[i] : 0;
    if (i < N_NODES) g_dinv[i] = rsqrtf(1.0f + (float)v);
    s[threadIdx.x] = v;
    __syncthreads();
#pragma unroll
    for (int off = 1; off < SCAN_B; off <<= 1) {
        int t = (threadIdx.x >= off) ? s[threadIdx.x - off] : 0;
        __syncthreads();
        s[threadIdx.x] += t;
        __syncthreads();
    }
    if (i < N_NODES) g_rowptr[i] = s[threadIdx.x] - v;
    if (threadIdx.x == SCAN_B - 1) g_bsum[blockIdx.x] = s[SCAN_B - 1];
}

__global__ void k_scan23() {
    __shared__ int s[128];
    __shared__ int ex[128];
    int t = threadIdx.x;
    int v = 0;
    if (t < 128) {
        v = (t < N_SCAN_BLOCKS) ? g_bsum[t] : 0;
        s[t] = v;
    }
    __syncthreads();
#pragma unroll
    for (int off = 1; off < 128; off <<= 1) {
        int tv = 0;
        if (t < 128 && t >= off) tv = s[t - off];
        __syncthreads();
        if (t < 128) s[t] += tv;
        __syncthreads();
    }
    if (t < 128) ex[t] = s[t] - v;   // exclusive
    __syncthreads();
    int i = blockIdx.x * blockDim.x + t;
    if (i < N_NODES) g_rowptr[i] += ex[i >> 10];
    if (i == 0) g_rowptr[N_NODES] = N_EDGES;
}

__global__ void k_fill(const void* __restrict__ buf) {
    int e = blockIdx.x * blockDim.x + threadIdx.x;
    if (e >= N_EDGES) return;
    unsigned p = g_epack[e];
    int c = (int)(p >> 15);
    int pos = (int)(p & 0x7FFFu);
    int r;
    if (g_is64) r = (int)((const long long*)buf)[e];
    else        r = ((const int*)buf)[e];
    int idx = g_rowptr[c] + pos;
    if (idx < N_EDGES) g_src[idx] = r;
}

__global__ void k_w2h(const float* __restrict__ Ws) {
    int i = blockIdx.x * blockDim.x + threadIdx.x;
    if (i < 3 * D * D) g_w16[i] = __float2half_rn(Ws[i]);
}

// ===========================================================================
// fp16 wmma GEMM (proven shape) with row_base + hs_out for chunk pipelining.
// ===========================================================================
#define LDH 136
#define GEMM_SMEM (2 * 128 * LDH * 2)      // 69632 B

template<bool FROM_EMB>
__global__ void __launch_bounds__(256, 2)
k_gemm(const __half* __restrict__ Wl, const float* __restrict__ emb,
       int row_base, __half* __restrict__ hs_out) {
    extern __shared__ __half smh[];
    __half* As = smh;                 // [128][LDH]
    __half* Wsm = smh + 128 * LDH;    // [128][LDH]

    const int tid = threadIdx.x;
    const int wid = tid >> 5;
    const int lane = tid & 31;
    const int wm = wid >> 1;
    const int wn = wid & 1;
    const int row0 = row_base + blockIdx.x * 128;

    for (int idx = tid; idx < 2048; idx += 256) {
        int r = idx >> 4, c8 = idx & 15;
        uint4 v = ((const uint4*)(Wl + r * D))[c8];
        *(uint4*)(Wsm + r * LDH + c8 * 8) = v;
    }
    for (int idx = tid; idx < 2048; idx += 256) {
        int r = idx >> 4, c8 = idx & 15;
        int row = row0 + r;
        uint4 v = make_uint4(0u, 0u, 0u, 0u);
        if (row < N_NODES) {
            if (FROM_EMB) {
                const float4* s = (const float4*)(emb + (size_t)row * D) + c8 * 2;
                float4 v0 = s[0], v1 = s[1];
                __half2 h;
                h = __floats2half2_rn(v0.x, v0.y); v.x = *(uint32_t*)&h;
                h = __floats2half2_rn(v0.z, v0.w); v.y = *(uint32_t*)&h;
                h = __floats2half2_rn(v1.x, v1.y); v.z = *(uint32_t*)&h;
                h = __floats2half2_rn(v1.z, v1.w); v.w = *(uint32_t*)&h;
            } else {
                v = ((const uint4*)(g_xh + (size_t)row * D))[c8];
            }
        }
        *(uint4*)(As + r * LDH + c8 * 8) = v;
    }
    __syncthreads();

    wmma::fragment<wmma::accumulator, 16, 16, 16, float> acc[2][4];
#pragma unroll
    for (int i = 0; i < 2; i++)
#pragma unroll
        for (int j = 0; j < 4; j++) wmma::fill_fragment(acc[i][j], 0.0f);

#pragma unroll
    for (int k = 0; k < 8; k++) {
        wmma::fragment<wmma::matrix_a, 16, 16, 16, __half, wmma::row_major> a[2];
        wmma::fragment<wmma::matrix_b, 16, 16, 16, __half, wmma::row_major> b[4];
#pragma unroll
        for (int i = 0; i < 2; i++)
            wmma::load_matrix_sync(a[i], As + (wm * 32 + i * 16) * LDH + k * 16,
                                   LDH);
#pragma unroll
        for (int j = 0; j < 4; j++)
            wmma::load_matrix_sync(b[j], Wsm + (k * 16) * LDH + wn * 64 + j * 16,
                                   LDH);
#pragma unroll
        for (int i = 0; i < 2; i++)
#pragma unroll
            for (int j = 0; j < 4; j++)
                wmma::mma_sync(acc[i][j], a[i], b[j], acc[i][j]);
    }

    __syncthreads();
    float* stage = reinterpret_cast<float*>(smh) + wid * (16 * 68);
#pragma unroll
    for (int i = 0; i < 2; i++) {
#pragma unroll
        for (int j = 0; j < 4; j++)
            wmma::store_matrix_sync(stage + j * 16, acc[i][j], 68,
                                    wmma::mem_row_major);
        __syncwarp();
        int r = lane >> 1;
        int ch = (lane & 1) * 32;
        int row = row0 + wm * 32 + i * 16 + r;
        float s = (row < N_NODES) ? g_dinv[row] : 0.0f;
        const float* src = stage + r * 68 + ch;
        if (row < N_NODES) {
            uint4* dst = (uint4*)(hs_out + (size_t)row * D + wn * 64 + ch);
#pragma unroll
            for (int q = 0; q < 4; q++) {
                uint4 o;
                __half2 h;
                h = __floats2half2_rn(src[q * 8 + 0] * s, src[q * 8 + 1] * s);
                o.x = *(uint32_t*)&h;
                h = __floats2half2_rn(src[q * 8 + 2] * s, src[q * 8 + 3] * s);
                o.y = *(uint32_t*)&h;
                h = __floats2half2_rn(src[q * 8 + 4] * s, src[q * 8 + 5] * s);
                o.z = *(uint32_t*)&h;
                h = __floats2half2_rn(src[q * 8 + 6] * s, src[q * 8 + 7] * s);
                o.w = *(uint32_t*)&h;
                dst[q] = o;
            }
        }
        __syncwarp();
    }
}

// ===========================================================================
// Aggregation (proven R12 shape) with node_base/count + hs_in.
// ===========================================================================
__global__ void __launch_bounds__(256)
k_aggregate(const float* __restrict__ bias, float* __restrict__ out,
            int use_out, int node_base, int node_count,
            const __half* __restrict__ hs_in) {
    int idx = (blockIdx.x * blockDim.x + threadIdx.x) >> 5;
    int lane = threadIdx.x & 31;
    if (idx >= node_count) return;
    int node = node_base + idx;

    float dinv_c = g_dinv[node];
    const uint2* HS = (const uint2*)hs_in;   // 32 uint2 per row

    uint2 v = HS[(size_t)node * 32 + lane];
    float2 f0 = __half22float2(*(__half2*)&v.x);
    float2 f1 = __half22float2(*(__half2*)&v.y);
    float4 acc0 = make_float4(f0.x, f0.y, f1.x, f1.y);
    float4 acc1 = make_float4(0.f, 0.f, 0.f, 0.f);

    int beg = g_rowptr[node];
    int end = g_rowptr[node + 1];
    for (int base = beg; base < end; base += 32) {
        int j = base + lane;
        int r = (j < end) ? g_src[j] : 0;
        int cnt = min(32, end - base);
        int k = 0;
        for (; k + 1 < cnt; k += 2) {
            int r0 = __shfl_sync(0xffffffffu, r, k);
            int r1 = __shfl_sync(0xffffffffu, r, k + 1);
            uint2 v0 = HS[(size_t)r0 * 32 + lane];
            uint2 v1 = HS[(size_t)r1 * 32 + lane];
            float2 a0 = __half22float2(*(__half2*)&v0.x);
            float2 a1 = __half22float2(*(__half2*)&v0.y);
            float2 b0 = __half22float2(*(__half2*)&v1.x);
            float2 b1 = __half22float2(*(__half2*)&v1.y);
            acc0.x += a0.x; acc0.y += a0.y; acc0.z += a1.x; acc0.w += a1.y;
            acc1.x += b0.x; acc1.y += b0.y; acc1.z += b1.x; acc1.w += b1.y;
        }
        if (k < cnt) {
            int r0 = __shfl_sync(0xffffffffu, r, k);
            uint2 v0 = HS[(size_t)r0 * 32 + lane];
            float2 a0 = __half22float2(*(__half2*)&v0.x);
            float2 a1 = __half22float2(*(__half2*)&v0.y);
            acc0.x += a0.x; acc0.y += a0.y; acc0.z += a1.x; acc0.w += a1.y;
        }
    }

    float4 bb = ((const float4*)bias)[lane];
    float4 x;
    x.x = fmaxf(fmaf(dinv_c, acc0.x + acc1.x, bb.x), 0.f);
    x.y = fmaxf(fmaf(dinv_c, acc0.y + acc1.y, bb.y), 0.f);
    x.z = fmaxf(fmaf(dinv_c, acc0.z + acc1.z, bb.z), 0.f);
    x.w = fmaxf(fmaf(dinv_c, acc0.w + acc1.w, bb.w), 0.f);

    if (use_out) {
        ((float4*)(out + (size_t)node * D))[lane] = x;
    } else {
        uint2 o;
        __half2 h;
        h = __floats2half2_rn(x.x, x.y); o.x = *(uint32_t*)&h;
        h = __floats2half2_rn(x.z, x.w); o.y = *(uint32_t*)&h;
        ((uint2*)(g_xh + (size_t)node * D))[lane] = o;
    }
}

// ===========================================================================
// Launch — two-stream pipeline:
//  s2: w2h | CSR finalize | gemm_{l+1}(chunk0) overlapped with agg_l(chunk1)
//  Double-buffered hs (hs0 layers 0/2, hs1 layer 1) removes the hs race.
// ===========================================================================
extern "C" void kernel_launch(void* const* d_in, const int* in_sizes, int n_in,
                              void* d_out, int out_size) {
    const void* edge = d_in[0];
    const float* emb = (const float*)d_in[1];
    const float* Ws  = (const float*)d_in[2];
    const float* bs  = (const float*)d_in[3];
    float* out = (float*)d_out;

    __half *w16, *hs0, *hs1;
    cudaGetSymbolAddress((void**)&w16, g_w16);
    cudaGetSymbolAddress((void**)&hs0, g_hs0);
    cudaGetSymbolAddress((void**)&hs1, g_hs1);

    static cudaStream_t s2;
    static cudaEvent_t e0, eW, e1, e2, eA0, eG1, eA1, eG2;
    static bool init_done = false;
    if (!init_done) {
        cudaFuncSetAttribute(k_gemm<true>,
                             cudaFuncAttributeMaxDynamicSharedMemorySize, GEMM_SMEM);
        cudaFuncSetAttribute(k_gemm<false>,
                             cudaFuncAttributeMaxDynamicSharedMemorySize, GEMM_SMEM);
        cudaStreamCreateWithFlags(&s2, cudaStreamNonBlocking);
        cudaEventCreateWithFlags(&e0, cudaEventDisableTiming);
        cudaEventCreateWithFlags(&eW, cudaEventDisableTiming);
        cudaEventCreateWithFlags(&e1, cudaEventDisableTiming);
        cudaEventCreateWithFlags(&e2, cudaEventDisableTiming);
        cudaEventCreateWithFlags(&eA0, cudaEventDisableTiming);
        cudaEventCreateWithFlags(&eG1, cudaEventDisableTiming);
        cudaEventCreateWithFlags(&eA1, cudaEventDisableTiming);
        cudaEventCreateWithFlags(&eG2, cudaEventDisableTiming);
        init_done = true;
    }

    const int nb_nodes = (N_NODES + 255) / 256;
    const int nb_edges = (N_EDGES + 255) / 256;
    const int gemm_full = N_PAD / 128;                  // 782
    const int gemm_half = gemm_full / 2;                // 391
    const int agg_c0 = (C0N * 32 + 255) / 256;          // 6256
    const int agg_c1 = (C1N * 32 + 255) / 256;          // 6244

    // s2: W conversion at the very start (independent of edges)
    cudaEventRecord(e0, 0);
    cudaStreamWaitEvent(s2, e0, 0);
    k_w2h<<<(3 * D * D + 255) / 256, 256, 0, s2>>>(Ws);
    cudaEventRecord(eW, s2);

    // main: edge decode + degree + scan1
    k_detect_zero<<<nb_nodes, 256>>>((const unsigned int*)edge);
    k_hist_pack<<<nb_edges, 256>>>(edge);
    k_scan1<<<N_SCAN_BLOCKS, SCAN_B>>>();

    // s2: CSR finalize, overlapped with GEMM-0 on main
    cudaEventRecord(e1, 0);
    cudaStreamWaitEvent(s2, e1, 0);
    k_scan23<<<nb_nodes, 256, 0, s2>>>();
    k_fill<<<nb_edges, 256, 0, s2>>>(edge);
    cudaEventRecord(e2, s2);

    // Layer 0 GEMM (full; needs dinv + w16)
    cudaStreamWaitEvent(0, eW, 0);
    k_gemm<true><<<gemm_full, 256, GEMM_SMEM>>>(w16, emb, 0, hs0);

    // --- Layer 0 agg, pipelined with layer-1 GEMM ---
    cudaStreamWaitEvent(0, e2, 0);
    k_aggregate<<<agg_c0, 256>>>(bs + 0 * D, out, 0, 0, C0N, hs0);
    cudaEventRecord(eA0, 0);
    k_aggregate<<<agg_c1, 256>>>(bs + 0 * D, out, 0, C0N, C1N, hs0);
    cudaStreamWaitEvent(s2, eA0, 0);
    k_gemm<false><<<gemm_half, 256, GEMM_SMEM, s2>>>(w16 + 1 * D * D, nullptr,
                                                     0, hs1);
    cudaEventRecord(eG1, s2);
    k_gemm<false><<<gemm_half, 256, GEMM_SMEM>>>(w16 + 1 * D * D, nullptr,
                                                 C0N, hs1);
    cudaStreamWaitEvent(0, eG1, 0);

    // --- Layer 1 agg, pipelined with layer-2 GEMM ---
    k_aggregate<<<agg_c0, 256>>>(bs + 1 * D, out, 0, 0, C0N, hs1);
    cudaEventRecord(eA1, 0);
    k_aggregate<<<agg_c1, 256>>>(bs + 1 * D, out, 0, C0N, C1N, hs1);
    cudaStreamWaitEvent(s2, eA1, 0);
    k_gemm<false><<<gemm_half, 256, GEMM_SMEM, s2>>>(w16 + 2 * D * D, nullptr,
                                                     0, hs0);
    cudaEventRecord(eG2, s2);
    k_gemm<false><<<gemm_half, 256, GEMM_SMEM>>>(w16 + 2 * D * D, nullptr,
                                                 C0N, hs0);
    cudaStreamWaitEvent(0, eG2, 0);

    // --- Layer 2 agg -> d_out ---
    k_aggregate<<<agg_c0, 256>>>(bs + 2 * D, out, 1, 0, C0N, hs0);
    k_aggregate<<<agg_c1, 256>>>(bs + 2 * D, out, 1, C0N, C1N, hs0);
}

// round 17
// speedup vs baseline: 1.0075x; 1.0075x over previous
#include <cuda_runtime.h>
#include <cuda_fp16.h>
#include <mma.h>
#include <cstdint>

#define N_NODES 100000
#define N_PAD   100096        // multiple of 128-row tiles
#define N_EDGES 1600000
#define D 128
#define SCAN_B 1024
#define N_SCAN_BLOCKS ((N_NODES + SCAN_B - 1) / SCAN_B)   // 98
#define C0N 50048             // chunk0 rows/nodes (391 gemm tiles)
#define C1N (N_NODES - C0N)   // 49952 nodes (chunk1 gemm covers to N_PAD)

using namespace nvcuda;

// Scratch (allocation-free rule: __device__ globals; zero-initialized)
__device__ __half g_hs0[(size_t)N_PAD * D];  // hs buffer, layers 0 & 2
__device__ __half g_hs1[(size_t)N_PAD * D];  // hs buffer, layer 1
__device__ __half g_xh[(size_t)N_PAD * D];   // activations, fp16 (pad rows 0)
__device__ __half g_w16[3 * D * D];          // weights, fp16
__device__ float  g_dinv[N_NODES];
__device__ int    g_is64;
__device__ unsigned g_epack[N_EDGES];        // (col<<15) | slot
__device__ int    g_cnt[N_NODES];
__device__ int    g_rowptr[N_NODES + 1];
__device__ int    g_src[N_EDGES];
__device__ int    g_bsum[N_SCAN_BLOCKS];

// ===========================================================================
// Setup (proven R12/R15 kernels)
// ===========================================================================
__global__ void k_detect_zero(const unsigned int* __restrict__ buf) {
    int i = blockIdx.x * blockDim.x + threadIdx.x;
    if (i < N_NODES) g_cnt[i] = 0;
    if (blockIdx.x == 0) {
        __shared__ unsigned int acc;
        if (threadIdx.x == 0) acc = 0u;
        __syncthreads();
        unsigned int local = 0u;
        for (int k = threadIdx.x; k < 4096; k += blockDim.x)
            local |= buf[2 * k + 1];
        atomicOr(&acc, local);
        __syncthreads();
        if (threadIdx.x == 0) g_is64 = (acc == 0u) ? 1 : 0;
    }
}

__global__ void k_hist_pack(const void* __restrict__ buf) {
    int e = blockIdx.x * blockDim.x + threadIdx.x;
    if (e >= N_EDGES) return;
    int c;
    if (g_is64) c = (int)((const long long*)buf)[e + N_EDGES];
    else        c = ((const int*)buf)[e + N_EDGES];
    int pos = atomicAdd(&g_cnt[c], 1);
    g_epack[e] = ((unsigned)c << 15) | ((unsigned)pos & 0x7FFFu);
}

__global__ void __launch_bounds__(SCAN_B)
k_scan1() {
    __shared__ int s[SCAN_B];
    int i = blockIdx.x * SCAN_B + threadIdx.x;
    int v = (i < N_NODES) ? g_cnt[i] : 0;
    if (i < N_NODES) g_dinv[i] = rsqrtf(1.0f + (float)v);
    s[threadIdx.x] = v;
    __syncthreads();
#pragma unroll
    for (int off = 1; off < SCAN_B; off <<= 1) {
        int t = (threadIdx.x >= off) ? s[threadIdx.x - off] : 0;
        __syncthreads();
        s[threadIdx.x] += t;
        __syncthreads();
    }
    if (i < N_NODES) g_rowptr[i] = s[threadIdx.x] - v;
    if (threadIdx.x == SCAN_B - 1) g_bsum[blockIdx.x] = s[SCAN_B - 1];
}

__global__ void k_scan23() {
    __shared__ int s[128];
    __shared__ int ex[128];
    int t = threadIdx.x;
    int v = 0;
    if (t < 128) {
        v = (t < N_SCAN_BLOCKS) ? g_bsum[t] : 0;
        s[t] = v;
    }
    __syncthreads();
#pragma unroll
    for (int off = 1; off < 128; off <<= 1) {
        int tv = 0;
        if (t < 128 && t >= off) tv = s[t - off];
        __syncthreads();
        if (t < 128) s[t] += tv;
        __syncthreads();
    }
    if (t < 128) ex[t] = s[t] - v;   // exclusive
    __syncthreads();
    int i = blockIdx.x * blockDim.x + t;
    if (i < N_NODES) g_rowptr[i] += ex[i >> 10];
    if (i == 0) g_rowptr[N_NODES] = N_EDGES;
}

__global__ void k_fill(const void* __restrict__ buf) {
    int e = blockIdx.x * blockDim.x + threadIdx.x;
    if (e >= N_EDGES) return;
    unsigned p = g_epack[e];
    int c = (int)(p >> 15);
    int pos = (int)(p & 0x7FFFu);
    int r;
    if (g_is64) r = (int)((const long long*)buf)[e];
    else        r = ((const int*)buf)[e];
    int idx = g_rowptr[c] + pos;
    if (idx < N_EDGES) g_src[idx] = r;
}

__global__ void k_w2h(const float* __restrict__ Ws) {
    int i = blockIdx.x * blockDim.x + threadIdx.x;
    if (i < 3 * D * D) g_w16[i] = __float2half_rn(Ws[i]);
}

// ===========================================================================
// fp16 wmma GEMM (proven shape) with row_base + hs_out for chunk pipelining.
// ===========================================================================
#define LDH 136
#define GEMM_SMEM (2 * 128 * LDH * 2)      // 69632 B

template<bool FROM_EMB>
__global__ void __launch_bounds__(256, 2)
k_gemm(const __half* __restrict__ Wl, const float* __restrict__ emb,
       int row_base, __half* __restrict__ hs_out) {
    extern __shared__ __half smh[];
    __half* As = smh;                 // [128][LDH]
    __half* Wsm = smh + 128 * LDH;    // [128][LDH]

    const int tid = threadIdx.x;
    const int wid = tid >> 5;
    const int lane = tid & 31;
    const int wm = wid >> 1;
    const int wn = wid & 1;
    const int row0 = row_base + blockIdx.x * 128;

    for (int idx = tid; idx < 2048; idx += 256) {
        int r = idx >> 4, c8 = idx & 15;
        uint4 v = ((const uint4*)(Wl + r * D))[c8];
        *(uint4*)(Wsm + r * LDH + c8 * 8) = v;
    }
    for (int idx = tid; idx < 2048; idx += 256) {
        int r = idx >> 4, c8 = idx & 15;
        int row = row0 + r;
        uint4 v = make_uint4(0u, 0u, 0u, 0u);
        if (row < N_NODES) {
            if (FROM_EMB) {
                const float4* s = (const float4*)(emb + (size_t)row * D) + c8 * 2;
                float4 v0 = s[0], v1 = s[1];
                __half2 h;
                h = __floats2half2_rn(v0.x, v0.y); v.x = *(uint32_t*)&h;
                h = __floats2half2_rn(v0.z, v0.w); v.y = *(uint32_t*)&h;
                h = __floats2half2_rn(v1.x, v1.y); v.z = *(uint32_t*)&h;
                h = __floats2half2_rn(v1.z, v1.w); v.w = *(uint32_t*)&h;
            } else {
                v = ((const uint4*)(g_xh + (size_t)row * D))[c8];
            }
        }
        *(uint4*)(As + r * LDH + c8 * 8) = v;
    }
    __syncthreads();

    wmma::fragment<wmma::accumulator, 16, 16, 16, float> acc[2][4];
#pragma unroll
    for (int i = 0; i < 2; i++)
#pragma unroll
        for (int j = 0; j < 4; j++) wmma::fill_fragment(acc[i][j], 0.0f);

#pragma unroll
    for (int k = 0; k < 8; k++) {
        wmma::fragment<wmma::matrix_a, 16, 16, 16, __half, wmma::row_major> a[2];
        wmma::fragment<wmma::matrix_b, 16, 16, 16, __half, wmma::row_major> b[4];
#pragma unroll
        for (int i = 0; i < 2; i++)
            wmma::load_matrix_sync(a[i], As + (wm * 32 + i * 16) * LDH + k * 16,
                                   LDH);
#pragma unroll
        for (int j = 0; j < 4; j++)
            wmma::load_matrix_sync(b[j], Wsm + (k * 16) * LDH + wn * 64 + j * 16,
                                   LDH);
#pragma unroll
        for (int i = 0; i < 2; i++)
#pragma unroll
            for (int j = 0; j < 4; j++)
                wmma::mma_sync(acc[i][j], a[i], b[j], acc[i][j]);
    }

    __syncthreads();
    float* stage = reinterpret_cast<float*>(smh) + wid * (16 * 68);
#pragma unroll
    for (int i = 0; i < 2; i++) {
#pragma unroll
        for (int j = 0; j < 4; j++)
            wmma::store_matrix_sync(stage + j * 16, acc[i][j], 68,
                                    wmma::mem_row_major);
        __syncwarp();
        int r = lane >> 1;
        int ch = (lane & 1) * 32;
        int row = row0 + wm * 32 + i * 16 + r;
        float s = (row < N_NODES) ? g_dinv[row] : 0.0f;
        const float* src = stage + r * 68 + ch;
        if (row < N_NODES) {
            uint4* dst = (uint4*)(hs_out + (size_t)row * D + wn * 64 + ch);
#pragma unroll
            for (int q = 0; q < 4; q++) {
                uint4 o;
                __half2 h;
                h = __floats2half2_rn(src[q * 8 + 0] * s, src[q * 8 + 1] * s);
                o.x = *(uint32_t*)&h;
                h = __floats2half2_rn(src[q * 8 + 2] * s, src[q * 8 + 3] * s);
                o.y = *(uint32_t*)&h;
                h = __floats2half2_rn(src[q * 8 + 4] * s, src[q * 8 + 5] * s);
                o.z = *(uint32_t*)&h;
                h = __floats2half2_rn(src[q * 8 + 6] * s, src[q * 8 + 7] * s);
                o.w = *(uint32_t*)&h;
                dst[q] = o;
            }
        }
        __syncwarp();
    }
}

// ===========================================================================
// Aggregation (proven R12 shape) with node_base/count + hs_in.
// ===========================================================================
__global__ void __launch_bounds__(256)
k_aggregate(const float* __restrict__ bias, float* __restrict__ out,
            int use_out, int node_base, int node_count,
            const __half* __restrict__ hs_in) {
    int idx = (blockIdx.x * blockDim.x + threadIdx.x) >> 5;
    int lane = threadIdx.x & 31;
    if (idx >= node_count) return;
    int node = node_base + idx;

    float dinv_c = g_dinv[node];
    const uint2* HS = (const uint2*)hs_in;   // 32 uint2 per row

    uint2 v = HS[(size_t)node * 32 + lane];
    float2 f0 = __half22float2(*(__half2*)&v.x);
    float2 f1 = __half22float2(*(__half2*)&v.y);
    float4 acc0 = make_float4(f0.x, f0.y, f1.x, f1.y);
    float4 acc1 = make_float4(0.f, 0.f, 0.f, 0.f);

    int beg = g_rowptr[node];
    int end = g_rowptr[node + 1];
    for (int base = beg; base < end; base += 32) {
        int j = base + lane;
        int r = (j < end) ? g_src[j] : 0;
        int cnt = min(32, end - base);
        int k = 0;
        for (; k + 1 < cnt; k += 2) {
            int r0 = __shfl_sync(0xffffffffu, r, k);
            int r1 = __shfl_sync(0xffffffffu, r, k + 1);
            uint2 v0 = HS[(size_t)r0 * 32 + lane];
            uint2 v1 = HS[(size_t)r1 * 32 + lane];
            float2 a0 = __half22float2(*(__half2*)&v0.x);
            float2 a1 = __half22float2(*(__half2*)&v0.y);
            float2 b0 = __half22float2(*(__half2*)&v1.x);
            float2 b1 = __half22float2(*(__half2*)&v1.y);
            acc0.x += a0.x; acc0.y += a0.y; acc0.z += a1.x; acc0.w += a1.y;
            acc1.x += b0.x; acc1.y += b0.y; acc1.z += b1.x; acc1.w += b1.y;
        }
        if (k < cnt) {
            int r0 = __shfl_sync(0xffffffffu, r, k);
            uint2 v0 = HS[(size_t)r0 * 32 + lane];
            float2 a0 = __half22float2(*(__half2*)&v0.x);
            float2 a1 = __half22float2(*(__half2*)&v0.y);
            acc0.x += a0.x; acc0.y += a0.y; acc0.z += a1.x; acc0.w += a1.y;
        }
    }

    float4 bb = ((const float4*)bias)[lane];
    float4 x;
    x.x = fmaxf(fmaf(dinv_c, acc0.x + acc1.x, bb.x), 0.f);
    x.y = fmaxf(fmaf(dinv_c, acc0.y + acc1.y, bb.y), 0.f);
    x.z = fmaxf(fmaf(dinv_c, acc0.z + acc1.z, bb.z), 0.f);
    x.w = fmaxf(fmaf(dinv_c, acc0.w + acc1.w, bb.w), 0.f);

    if (use_out) {
        ((float4*)(out + (size_t)node * D))[lane] = x;
    } else {
        uint2 o;
        __half2 h;
        h = __floats2half2_rn(x.x, x.y); o.x = *(uint32_t*)&h;
        h = __floats2half2_rn(x.z, x.w); o.y = *(uint32_t*)&h;
        ((uint2*)(g_xh + (size_t)node * D))[lane] = o;
    }
}

// ===========================================================================
// Launch — two-stream pipeline:
//  s2: w2h | CSR finalize | gemm_{l+1}(chunk0) overlapped with agg_l(chunk1)
//  Double-buffered hs (hs0 layers 0/2, hs1 layer 1) removes the hs race.
// ===========================================================================
extern "C" void kernel_launch(void* const* d_in, const int* in_sizes, int n_in,
                              void* d_out, int out_size) {
    const void* edge = d_in[0];
    const float* emb = (const float*)d_in[1];
    const float* Ws  = (const float*)d_in[2];
    const float* bs  = (const float*)d_in[3];
    float* out = (float*)d_out;

    __half *w16, *hs0, *hs1;
    cudaGetSymbolAddress((void**)&w16, g_w16);
    cudaGetSymbolAddress((void**)&hs0, g_hs0);
    cudaGetSymbolAddress((void**)&hs1, g_hs1);

    static cudaStream_t s2;
    static cudaEvent_t e0, eW, e1, e2, eA0, eG1, eA1, eG2;
    static bool init_done = false;
    if (!init_done) {
        cudaFuncSetAttribute(k_gemm<true>,
                             cudaFuncAttributeMaxDynamicSharedMemorySize, GEMM_SMEM);
        cudaFuncSetAttribute(k_gemm<false>,
                             cudaFuncAttributeMaxDynamicSharedMemorySize, GEMM_SMEM);
        cudaStreamCreateWithFlags(&s2, cudaStreamNonBlocking);
        cudaEventCreateWithFlags(&e0, cudaEventDisableTiming);
        cudaEventCreateWithFlags(&eW, cudaEventDisableTiming);
        cudaEventCreateWithFlags(&e1, cudaEventDisableTiming);
        cudaEventCreateWithFlags(&e2, cudaEventDisableTiming);
        cudaEventCreateWithFlags(&eA0, cudaEventDisableTiming);
        cudaEventCreateWithFlags(&eG1, cudaEventDisableTiming);
        cudaEventCreateWithFlags(&eA1, cudaEventDisableTiming);
        cudaEventCreateWithFlags(&eG2, cudaEventDisableTiming);
        init_done = true;
    }

    const int nb_nodes = (N_NODES + 255) / 256;
    const int nb_edges = (N_EDGES + 255) / 256;
    const int gemm_full = N_PAD / 128;                  // 782
    const int gemm_half = gemm_full / 2;                // 391
    const int agg_c0 = (C0N * 32 + 255) / 256;          // 6256
    const int agg_c1 = (C1N * 32 + 255) / 256;          // 6244

    // s2: W conversion at the very start (independent of edges)
    cudaEventRecord(e0, 0);
    cudaStreamWaitEvent(s2, e0, 0);
    k_w2h<<<(3 * D * D + 255) / 256, 256, 0, s2>>>(Ws);
    cudaEventRecord(eW, s2);

    // main: edge decode + degree + scan1
    k_detect_zero<<<nb_nodes, 256>>>((const unsigned int*)edge);
    k_hist_pack<<<nb_edges, 256>>>(edge);
    k_scan1<<<N_SCAN_BLOCKS, SCAN_B>>>();

    // s2: CSR finalize, overlapped with GEMM-0 on main
    cudaEventRecord(e1, 0);
    cudaStreamWaitEvent(s2, e1, 0);
    k_scan23<<<nb_nodes, 256, 0, s2>>>();
    k_fill<<<nb_edges, 256, 0, s2>>>(edge);
    cudaEventRecord(e2, s2);

    // Layer 0 GEMM (full; needs dinv + w16)
    cudaStreamWaitEvent(0, eW, 0);
    k_gemm<true><<<gemm_full, 256, GEMM_SMEM>>>(w16, emb, 0, hs0);

    // --- Layer 0 agg, pipelined with layer-1 GEMM ---
    cudaStreamWaitEvent(0, e2, 0);
    k_aggregate<<<agg_c0, 256>>>(bs + 0 * D, out, 0, 0, C0N, hs0);
    cudaEventRecord(eA0, 0);
    k_aggregate<<<agg_c1, 256>>>(bs + 0 * D, out, 0, C0N, C1N, hs0);
    cudaStreamWaitEvent(s2, eA0, 0);
    k_gemm<false><<<gemm_half, 256, GEMM_SMEM, s2>>>(w16 + 1 * D * D, nullptr,
                                                     0, hs1);
    cudaEventRecord(eG1, s2);
    k_gemm<false><<<gemm_half, 256, GEMM_SMEM>>>(w16 + 1 * D * D, nullptr,
                                                 C0N, hs1);
    cudaStreamWaitEvent(0, eG1, 0);

    // --- Layer 1 agg, pipelined with layer-2 GEMM ---
    k_aggregate<<<agg_c0, 256>>>(bs + 1 * D, out, 0, 0, C0N, hs1);
    cudaEventRecord(eA1, 0);
    k_aggregate<<<agg_c1, 256>>>(bs + 1 * D, out, 0, C0N, C1N, hs1);
    cudaStreamWaitEvent(s2, eA1, 0);
    k_gemm<false><<<gemm_half, 256, GEMM_SMEM, s2>>>(w16 + 2 * D * D, nullptr,
                                                     0, hs0);
    cudaEventRecord(eG2, s2);
    k_gemm<false><<<gemm_half, 256, GEMM_SMEM>>>(w16 + 2 * D * D, nullptr,
                                                 C0N, hs0);
    cudaStreamWaitEvent(0, eG2, 0);

    // --- Layer 2 agg -> d_out ---
    k_aggregate<<<agg_c0, 256>>>(bs + 2 * D, out, 1, 0, C0N, hs0);
    k_aggregate<<<agg_c1, 256>>>(bs + 2 * D, out, 1, C0N, C1N, hs0);
}